// round 4
// baseline (speedup 1.0000x reference)
#include <cuda_runtime.h>

#define EPS 1e-4f
#define NDIM 512

__device__ __forceinline__ float4 z4f() { return make_float4(0.f, 0.f, 0.f, 0.f); }
__device__ __forceinline__ void pf_l1(const void* p) {
    asm volatile("prefetch.global.L1 [%0];" :: "l"(p));
}

__global__ __launch_bounds__(1024, 1)
void sinkhorn_kernel(const float* __restrict__ s,
                     const int* __restrict__ nrows,
                     float* __restrict__ out) {
    extern __shared__ __align__(16) float red[];        // 32*512 floats = 64 KB
    __shared__ __align__(16) float c_sh[NDIM];
    __shared__ float ssumA[32];
    __shared__ float ssumB[32];

    const int b    = blockIdx.x;
    const int tid  = threadIdx.x;
    const int lane = tid & 31;
    const int wid  = tid >> 5;
    const int n    = nrows[b];
    const bool g2  = (n > 256);
    const bool g3  = (n > 384);
    const float* __restrict__ S = s   + (size_t)b * (NDIM * NDIM);
    float* __restrict__       O = out + (size_t)b * (NDIM * NDIM);
    const float4* __restrict__ c4s = (const float4*)c_sh;

    // ======================= iter 0: column pass (r = 1), 4-deep MLP ============
    {
        const int j4    = (tid & 127) << 2;
        const int slice = tid >> 7;                      // 0..7
        float4 a0 = z4f(), a1 = z4f(), a2 = z4f(), a3 = z4f();
        if (j4 < n) {
            int i = slice;
            for (; i + 24 < n; i += 32) {
                float4 v0 = *(const float4*)(S + (size_t)(i)      * NDIM + j4);
                float4 v1 = *(const float4*)(S + (size_t)(i + 8)  * NDIM + j4);
                float4 v2 = *(const float4*)(S + (size_t)(i + 16) * NDIM + j4);
                float4 v3 = *(const float4*)(S + (size_t)(i + 24) * NDIM + j4);
                a0.x += v0.x; a0.y += v0.y; a0.z += v0.z; a0.w += v0.w;
                a1.x += v1.x; a1.y += v1.y; a1.z += v1.z; a1.w += v1.w;
                a2.x += v2.x; a2.y += v2.y; a2.z += v2.z; a2.w += v2.w;
                a3.x += v3.x; a3.y += v3.y; a3.z += v3.z; a3.w += v3.w;
            }
            for (; i < n; i += 8) {
                float4 v0 = *(const float4*)(S + (size_t)i * NDIM + j4);
                a0.x += v0.x; a0.y += v0.y; a0.z += v0.z; a0.w += v0.w;
            }
            a0.x += a1.x + a2.x + a3.x; a0.y += a1.y + a2.y + a3.y;
            a0.z += a1.z + a2.z + a3.z; a0.w += a1.w + a2.w + a3.w;
        }
        *(float4*)(red + slice * NDIM + j4) = a0;
        __syncthreads();

        float cv = 0.0f;
        if (tid < n) {
            float cs = 0.0f;
            #pragma unroll
            for (int ss = 0; ss < 8; ++ss) cs += red[ss * NDIM + tid];
            cv = 1.0f / (cs + EPS * (float)n);
        }
        if (tid < NDIM) c_sh[tid] = cv;
        float v = cv;
        #pragma unroll
        for (int o = 16; o; o >>= 1) v += __shfl_xor_sync(0xffffffffu, v, o);
        if (lane == 0) ssumB[wid] = v;
        __syncthreads();
    }
    float sum_c = 0.0f;
    #pragma unroll
    for (int k = 0; k < 32; ++k) sum_c += ssumB[k];

    // ============== 4 fused passes: row(2f+1) + col(2f+2) with L1 prefetch ======
    #pragma unroll 1
    for (int f = 0; f < 4; ++f) {
        const float eps_c = EPS * sum_c;
        float4 acc0 = z4f(), acc1 = z4f(), acc2 = z4f(), acc3 = z4f();
        float rpart = 0.0f;

        for (int i = wid; i < n; i += 32) {
            const int inx = i + 32;
            if (inx < n)
                pf_l1((const char*)(S + (size_t)inx * NDIM) + (lane << 6));

            const float4* __restrict__ row = (const float4*)(S + (size_t)i * NDIM);
            float4 v0 = row[lane];
            float4 v1 = row[lane + 32];
            float4 v2 = z4f(), v3 = z4f();
            if (g2) v2 = row[lane + 64];
            if (g3) v3 = row[lane + 96];
            float4 c0 = c4s[lane], c1 = c4s[lane + 32];
            float4 c2 = c4s[lane + 64], c3 = c4s[lane + 96];

            float d0 = 0.f, d1 = 0.f, d2 = 0.f, d3 = 0.f;
            d0 = fmaf(v0.x, c0.x, d0); d1 = fmaf(v0.y, c0.y, d1);
            d2 = fmaf(v0.z, c0.z, d2); d3 = fmaf(v0.w, c0.w, d3);
            d0 = fmaf(v1.x, c1.x, d0); d1 = fmaf(v1.y, c1.y, d1);
            d2 = fmaf(v1.z, c1.z, d2); d3 = fmaf(v1.w, c1.w, d3);
            d0 = fmaf(v2.x, c2.x, d0); d1 = fmaf(v2.y, c2.y, d1);
            d2 = fmaf(v2.z, c2.z, d2); d3 = fmaf(v2.w, c2.w, d3);
            d0 = fmaf(v3.x, c3.x, d0); d1 = fmaf(v3.y, c3.y, d1);
            d2 = fmaf(v3.z, c3.z, d2); d3 = fmaf(v3.w, c3.w, d3);
            float t = (d0 + d1) + (d2 + d3);
            #pragma unroll
            for (int o = 16; o; o >>= 1) t += __shfl_xor_sync(0xffffffffu, t, o);

            const float ri = 1.0f / (t + eps_c);
            rpart += ri;

            acc0.x = fmaf(ri, v0.x, acc0.x); acc0.y = fmaf(ri, v0.y, acc0.y);
            acc0.z = fmaf(ri, v0.z, acc0.z); acc0.w = fmaf(ri, v0.w, acc0.w);
            acc1.x = fmaf(ri, v1.x, acc1.x); acc1.y = fmaf(ri, v1.y, acc1.y);
            acc1.z = fmaf(ri, v1.z, acc1.z); acc1.w = fmaf(ri, v1.w, acc1.w);
            acc2.x = fmaf(ri, v2.x, acc2.x); acc2.y = fmaf(ri, v2.y, acc2.y);
            acc2.z = fmaf(ri, v2.z, acc2.z); acc2.w = fmaf(ri, v2.w, acc2.w);
            acc3.x = fmaf(ri, v3.x, acc3.x); acc3.y = fmaf(ri, v3.y, acc3.y);
            acc3.z = fmaf(ri, v3.z, acc3.z); acc3.w = fmaf(ri, v3.w, acc3.w);
        }

        float4* __restrict__ rw = (float4*)(red + wid * NDIM);
        rw[lane]      = acc0;
        rw[lane + 32] = acc1;
        rw[lane + 64] = acc2;
        rw[lane + 96] = acc3;
        if (lane == 0) ssumA[wid] = rpart;
        __syncthreads();

        float sum_r = 0.0f;
        #pragma unroll
        for (int k = 0; k < 32; ++k) sum_r += ssumA[k];

        float cv = 0.0f;
        if (tid < n) {
            float cs = 0.0f;
            #pragma unroll
            for (int w = 0; w < 32; ++w) cs += red[w * NDIM + tid];
            cv = 1.0f / (cs + EPS * sum_r);
        }
        if (tid < NDIM) c_sh[tid] = cv;
        float v = cv;
        #pragma unroll
        for (int o = 16; o; o >>= 1) v += __shfl_xor_sync(0xffffffffu, v, o);
        if (lane == 0) ssumB[wid] = v;
        __syncthreads();
        sum_c = 0.0f;
        #pragma unroll
        for (int k = 0; k < 32; ++k) sum_c += ssumB[k];
    }

    // ============== final pass: row step (iter 9) fused with output write =======
    {
        const float eps_c = EPS * sum_c;
        for (int i = wid; i < n; i += 32) {
            const int inx = i + 32;
            if (inx < n)
                pf_l1((const char*)(S + (size_t)inx * NDIM) + (lane << 6));

            const float4* __restrict__ row = (const float4*)(S + (size_t)i * NDIM);
            float4* __restrict__ orow = (float4*)(O + (size_t)i * NDIM);
            float4 v0 = __ldcs(row + lane);
            float4 v1 = __ldcs(row + lane + 32);
            float4 v2 = z4f(), v3 = z4f();
            if (g2) v2 = __ldcs(row + lane + 64);
            if (g3) v3 = __ldcs(row + lane + 96);
            float4 c0 = c4s[lane], c1 = c4s[lane + 32];
            float4 c2 = c4s[lane + 64], c3 = c4s[lane + 96];

            float d0 = 0.f, d1 = 0.f, d2 = 0.f, d3 = 0.f;
            d0 = fmaf(v0.x, c0.x, d0); d1 = fmaf(v0.y, c0.y, d1);
            d2 = fmaf(v0.z, c0.z, d2); d3 = fmaf(v0.w, c0.w, d3);
            d0 = fmaf(v1.x, c1.x, d0); d1 = fmaf(v1.y, c1.y, d1);
            d2 = fmaf(v1.z, c1.z, d2); d3 = fmaf(v1.w, c1.w, d3);
            d0 = fmaf(v2.x, c2.x, d0); d1 = fmaf(v2.y, c2.y, d1);
            d2 = fmaf(v2.z, c2.z, d2); d3 = fmaf(v2.w, c2.w, d3);
            d0 = fmaf(v3.x, c3.x, d0); d1 = fmaf(v3.y, c3.y, d1);
            d2 = fmaf(v3.z, c3.z, d2); d3 = fmaf(v3.w, c3.w, d3);
            float t = (d0 + d1) + (d2 + d3);
            #pragma unroll
            for (int o = 16; o; o >>= 1) t += __shfl_xor_sync(0xffffffffu, t, o);
            const float ri = 1.0f / (t + eps_c);

            float4 w;
            w.x = (v0.x + EPS) * ri * c0.x; w.y = (v0.y + EPS) * ri * c0.y;
            w.z = (v0.z + EPS) * ri * c0.z; w.w = (v0.w + EPS) * ri * c0.w;
            __stcs(orow + lane, w);
            w.x = (v1.x + EPS) * ri * c1.x; w.y = (v1.y + EPS) * ri * c1.y;
            w.z = (v1.z + EPS) * ri * c1.z; w.w = (v1.w + EPS) * ri * c1.w;
            __stcs(orow + lane + 32, w);
            w.x = (v2.x + EPS) * ri * c2.x; w.y = (v2.y + EPS) * ri * c2.y;
            w.z = (v2.z + EPS) * ri * c2.z; w.w = (v2.w + EPS) * ri * c2.w;
            __stcs(orow + lane + 64, w);
            w.x = (v3.x + EPS) * ri * c3.x; w.y = (v3.y + EPS) * ri * c3.y;
            w.z = (v3.z + EPS) * ri * c3.z; w.w = (v3.w + EPS) * ri * c3.w;
            __stcs(orow + lane + 96, w);
        }
        // zero-fill rows i >= n
        float4* __restrict__ O4 = (float4*)O;
        const float4 z = z4f();
        for (int idx = n * 128 + tid; idx < NDIM * 128; idx += 1024)
            __stcs(O4 + idx, z);
    }
}

extern "C" void kernel_launch(void* const* d_in, const int* in_sizes, int n_in,
                              void* d_out, int out_size) {
    const float* s     = (const float*)d_in[0];
    const int*   nrows = (const int*)d_in[1];
    float*       out   = (float*)d_out;
    const int B = in_sizes[1];
    const int shbytes = 32 * NDIM * sizeof(float);   // 64 KB dynamic
    static bool attr_set = false;
    if (!attr_set) {
        cudaFuncSetAttribute(sinkhorn_kernel,
                             cudaFuncAttributeMaxDynamicSharedMemorySize, shbytes);
        attr_set = true;
    }
    sinkhorn_kernel<<<B, 1024, shbytes>>>(s, nrows, out);
}

// round 5
// speedup vs baseline: 1.0417x; 1.0417x over previous
#include <cuda_runtime.h>
#include <cuda_fp16.h>

#define EPS 1e-4f
#define NDIM 512
#define H2_PER_SAMPLE (NDIM * (NDIM / 2))   // 131072 half2 per sample

__device__ __half2 g_half[128 * H2_PER_SAMPLE];   // 64 MB scratch, zero-init

__device__ __forceinline__ float4 z4f() { return make_float4(0.f, 0.f, 0.f, 0.f); }

__device__ __forceinline__ float2 pack_h4(float4 v) {
    __half2 h0 = __floats2half2_rn(v.x, v.y);
    __half2 h1 = __floats2half2_rn(v.z, v.w);
    float2 r;
    r.x = __uint_as_float(*reinterpret_cast<unsigned*>(&h0));
    r.y = __uint_as_float(*reinterpret_cast<unsigned*>(&h1));
    return r;
}
__device__ __forceinline__ float2 h2f(unsigned u) {
    __half2 h = *reinterpret_cast<__half2*>(&u);
    return __half22float2(h);
}

__global__ __launch_bounds__(1024, 1)
void sinkhorn_kernel(const float* __restrict__ s,
                     const int* __restrict__ nrows,
                     float* __restrict__ out) {
    extern __shared__ __align__(16) float red[];        // 32*512 floats = 64 KB
    __shared__ __align__(16) float c_sh[NDIM];
    __shared__ float ssumA[32];
    __shared__ float ssumB[32];

    const int b    = blockIdx.x;
    const int tid  = threadIdx.x;
    const int lane = tid & 31;
    const int wid  = tid >> 5;
    const int n    = nrows[b];
    const bool g2  = (n > 256);
    const float* __restrict__ S = s   + (size_t)b * (NDIM * NDIM);
    float* __restrict__       O = out + (size_t)b * (NDIM * NDIM);
    __half2* __restrict__     H = g_half + (size_t)b * H2_PER_SAMPLE;
    const float4* __restrict__ c4s = (const float4*)c_sh;

    // ========== pass 0: column sums (r = 1) + fp16 conversion of active rows ====
    {
        const int j4    = (tid & 127) << 2;
        const int slice = tid >> 7;                      // 0..7
        const int jh    = j4 >> 1;                       // half2 col index
        float4 a0 = z4f(), a1 = z4f(), a2 = z4f(), a3 = z4f();
        if (j4 < n) {
            int i = slice;
            for (; i + 24 < n; i += 32) {
                float4 v0 = *(const float4*)(S + (size_t)(i)      * NDIM + j4);
                float4 v1 = *(const float4*)(S + (size_t)(i + 8)  * NDIM + j4);
                float4 v2 = *(const float4*)(S + (size_t)(i + 16) * NDIM + j4);
                float4 v3 = *(const float4*)(S + (size_t)(i + 24) * NDIM + j4);
                a0.x += v0.x; a0.y += v0.y; a0.z += v0.z; a0.w += v0.w;
                a1.x += v1.x; a1.y += v1.y; a1.z += v1.z; a1.w += v1.w;
                a2.x += v2.x; a2.y += v2.y; a2.z += v2.z; a2.w += v2.w;
                a3.x += v3.x; a3.y += v3.y; a3.z += v3.z; a3.w += v3.w;
                *(float2*)(H + (size_t)(i)      * (NDIM/2) + jh) = pack_h4(v0);
                *(float2*)(H + (size_t)(i + 8)  * (NDIM/2) + jh) = pack_h4(v1);
                *(float2*)(H + (size_t)(i + 16) * (NDIM/2) + jh) = pack_h4(v2);
                *(float2*)(H + (size_t)(i + 24) * (NDIM/2) + jh) = pack_h4(v3);
            }
            for (; i < n; i += 8) {
                float4 v0 = *(const float4*)(S + (size_t)i * NDIM + j4);
                a0.x += v0.x; a0.y += v0.y; a0.z += v0.z; a0.w += v0.w;
                *(float2*)(H + (size_t)i * (NDIM/2) + jh) = pack_h4(v0);
            }
            a0.x += a1.x + a2.x + a3.x; a0.y += a1.y + a2.y + a3.y;
            a0.z += a1.z + a2.z + a3.z; a0.w += a1.w + a2.w + a3.w;
        }
        *(float4*)(red + slice * NDIM + j4) = a0;
        __syncthreads();

        float cv = 0.0f;
        if (tid < n) {
            float cs = 0.0f;
            #pragma unroll
            for (int ss = 0; ss < 8; ++ss) cs += red[ss * NDIM + tid];
            cv = 1.0f / (cs + EPS * (float)n);
        }
        if (tid < NDIM) c_sh[tid] = cv;
        float v = cv;
        #pragma unroll
        for (int o = 16; o; o >>= 1) v += __shfl_xor_sync(0xffffffffu, v, o);
        if (lane == 0) ssumB[wid] = v;
        __syncthreads();
    }
    float sum_c = 0.0f;
    #pragma unroll
    for (int k = 0; k < 32; ++k) sum_c += ssumB[k];

    // ========== 4 fused passes: row(2f+1) + col(2f+2) reading the fp16 copy =====
    #pragma unroll 1
    for (int f = 0; f < 4; ++f) {
        const float eps_c = EPS * sum_c;
        float4 acc0 = z4f(), acc1 = z4f(), acc2 = z4f(), acc3 = z4f();
        float rpart = 0.0f;

        for (int i = wid; i < n; i += 32) {
            const uint4* __restrict__ rowH =
                (const uint4*)(H + (size_t)i * (NDIM / 2));
            uint4 u0 = rowH[lane];                       // cols 8*lane .. +7
            uint4 u1 = make_uint4(0u, 0u, 0u, 0u);
            if (g2) u1 = rowH[lane + 32];                // cols 256+8*lane .. +7

            float4 c0 = c4s[lane * 2],      c1 = c4s[lane * 2 + 1];
            float4 c2 = c4s[64 + lane * 2], c3 = c4s[64 + lane * 2 + 1];

            float2 f0 = h2f(u0.x), f1 = h2f(u0.y), f2 = h2f(u0.z), f3 = h2f(u0.w);
            float2 f4 = h2f(u1.x), f5 = h2f(u1.y), f6 = h2f(u1.z), f7 = h2f(u1.w);

            float d0 = 0.f, d1 = 0.f, d2 = 0.f, d3 = 0.f;
            d0 = fmaf(f0.x, c0.x, d0); d1 = fmaf(f0.y, c0.y, d1);
            d2 = fmaf(f1.x, c0.z, d2); d3 = fmaf(f1.y, c0.w, d3);
            d0 = fmaf(f2.x, c1.x, d0); d1 = fmaf(f2.y, c1.y, d1);
            d2 = fmaf(f3.x, c1.z, d2); d3 = fmaf(f3.y, c1.w, d3);
            d0 = fmaf(f4.x, c2.x, d0); d1 = fmaf(f4.y, c2.y, d1);
            d2 = fmaf(f5.x, c2.z, d2); d3 = fmaf(f5.y, c2.w, d3);
            d0 = fmaf(f6.x, c3.x, d0); d1 = fmaf(f6.y, c3.y, d1);
            d2 = fmaf(f7.x, c3.z, d2); d3 = fmaf(f7.y, c3.w, d3);
            float t = (d0 + d1) + (d2 + d3);
            #pragma unroll
            for (int o = 16; o; o >>= 1) t += __shfl_xor_sync(0xffffffffu, t, o);

            const float ri = 1.0f / (t + eps_c);
            rpart += ri;

            acc0.x = fmaf(ri, f0.x, acc0.x); acc0.y = fmaf(ri, f0.y, acc0.y);
            acc0.z = fmaf(ri, f1.x, acc0.z); acc0.w = fmaf(ri, f1.y, acc0.w);
            acc1.x = fmaf(ri, f2.x, acc1.x); acc1.y = fmaf(ri, f2.y, acc1.y);
            acc1.z = fmaf(ri, f3.x, acc1.z); acc1.w = fmaf(ri, f3.y, acc1.w);
            acc2.x = fmaf(ri, f4.x, acc2.x); acc2.y = fmaf(ri, f4.y, acc2.y);
            acc2.z = fmaf(ri, f5.x, acc2.z); acc2.w = fmaf(ri, f5.y, acc2.w);
            acc3.x = fmaf(ri, f6.x, acc3.x); acc3.y = fmaf(ri, f6.y, acc3.y);
            acc3.z = fmaf(ri, f7.x, acc3.z); acc3.w = fmaf(ri, f7.y, acc3.w);
        }

        float4* __restrict__ rw = (float4*)(red + wid * NDIM);
        rw[lane * 2]          = acc0;
        rw[lane * 2 + 1]      = acc1;
        rw[64 + lane * 2]     = acc2;
        rw[64 + lane * 2 + 1] = acc3;
        if (lane == 0) ssumA[wid] = rpart;
        __syncthreads();

        float sum_r = 0.0f;
        #pragma unroll
        for (int k = 0; k < 32; ++k) sum_r += ssumA[k];

        float cv = 0.0f;
        if (tid < n) {
            float cs = 0.0f;
            #pragma unroll
            for (int w = 0; w < 32; ++w) cs += red[w * NDIM + tid];
            cv = 1.0f / (cs + EPS * sum_r);
        }
        if (tid < NDIM) c_sh[tid] = cv;
        float v = cv;
        #pragma unroll
        for (int o = 16; o; o >>= 1) v += __shfl_xor_sync(0xffffffffu, v, o);
        if (lane == 0) ssumB[wid] = v;
        __syncthreads();
        sum_c = 0.0f;
        #pragma unroll
        for (int k = 0; k < 32; ++k) sum_c += ssumB[k];
    }

    // ========== final pass: row step (iter 9) on fp32 S, fused output write =====
    {
        const float eps_c = EPS * sum_c;
        const bool g3 = (n > 384);
        for (int i = wid; i < n; i += 32) {
            const float4* __restrict__ row = (const float4*)(S + (size_t)i * NDIM);
            float4* __restrict__ orow = (float4*)(O + (size_t)i * NDIM);
            float4 v0 = __ldcs(row + lane);
            float4 v1 = __ldcs(row + lane + 32);
            float4 v2 = z4f(), v3 = z4f();
            if (g2) v2 = __ldcs(row + lane + 64);
            if (g3) v3 = __ldcs(row + lane + 96);
            float4 c0 = c4s[lane], c1 = c4s[lane + 32];
            float4 c2 = c4s[lane + 64], c3 = c4s[lane + 96];

            float d0 = 0.f, d1 = 0.f, d2 = 0.f, d3 = 0.f;
            d0 = fmaf(v0.x, c0.x, d0); d1 = fmaf(v0.y, c0.y, d1);
            d2 = fmaf(v0.z, c0.z, d2); d3 = fmaf(v0.w, c0.w, d3);
            d0 = fmaf(v1.x, c1.x, d0); d1 = fmaf(v1.y, c1.y, d1);
            d2 = fmaf(v1.z, c1.z, d2); d3 = fmaf(v1.w, c1.w, d3);
            d0 = fmaf(v2.x, c2.x, d0); d1 = fmaf(v2.y, c2.y, d1);
            d2 = fmaf(v2.z, c2.z, d2); d3 = fmaf(v2.w, c2.w, d3);
            d0 = fmaf(v3.x, c3.x, d0); d1 = fmaf(v3.y, c3.y, d1);
            d2 = fmaf(v3.z, c3.z, d2); d3 = fmaf(v3.w, c3.w, d3);
            float t = (d0 + d1) + (d2 + d3);
            #pragma unroll
            for (int o = 16; o; o >>= 1) t += __shfl_xor_sync(0xffffffffu, t, o);
            const float ri = 1.0f / (t + eps_c);

            float4 w;
            w.x = (v0.x + EPS) * ri * c0.x; w.y = (v0.y + EPS) * ri * c0.y;
            w.z = (v0.z + EPS) * ri * c0.z; w.w = (v0.w + EPS) * ri * c0.w;
            __stcs(orow + lane, w);
            w.x = (v1.x + EPS) * ri * c1.x; w.y = (v1.y + EPS) * ri * c1.y;
            w.z = (v1.z + EPS) * ri * c1.z; w.w = (v1.w + EPS) * ri * c1.w;
            __stcs(orow + lane + 32, w);
            w.x = (v2.x + EPS) * ri * c2.x; w.y = (v2.y + EPS) * ri * c2.y;
            w.z = (v2.z + EPS) * ri * c2.z; w.w = (v2.w + EPS) * ri * c2.w;
            __stcs(orow + lane + 64, w);
            w.x = (v3.x + EPS) * ri * c3.x; w.y = (v3.y + EPS) * ri * c3.y;
            w.z = (v3.z + EPS) * ri * c3.z; w.w = (v3.w + EPS) * ri * c3.w;
            __stcs(orow + lane + 96, w);
        }
        // zero-fill rows i >= n
        float4* __restrict__ O4 = (float4*)O;
        const float4 z = z4f();
        for (int idx = n * 128 + tid; idx < NDIM * 128; idx += 1024)
            __stcs(O4 + idx, z);
    }
}

extern "C" void kernel_launch(void* const* d_in, const int* in_sizes, int n_in,
                              void* d_out, int out_size) {
    const float* s     = (const float*)d_in[0];
    const int*   nrows = (const int*)d_in[1];
    float*       out   = (float*)d_out;
    const int B = in_sizes[1];
    const int shbytes = 32 * NDIM * sizeof(float);   // 64 KB dynamic
    static bool attr_set = false;
    if (!attr_set) {
        cudaFuncSetAttribute(sinkhorn_kernel,
                             cudaFuncAttributeMaxDynamicSharedMemorySize, shbytes);
        attr_set = true;
    }
    sinkhorn_kernel<<<B, 1024, shbytes>>>(s, nrows, out);
}